// round 15
// baseline (speedup 1.0000x reference)
#include <cuda_runtime.h>
#include <cstdint>

#define HID 256
#define H4  64            // HID/4 float4 per row
#define NB  1024          // number of graphs
#define EPS 1e-5f
#define MLP_BLOCKS 128
#define POOL_BLOCKS 2048
#define TAIL_CACHED 448   // last pool blocks load x with L2-caching (~112MB)

// scratch (allocation-free rule: static __device__ globals; zero-initialized
// at module load; each call's gather re-zeroes them for the next call)
__device__ float g_hpool[NB * HID];
__device__ float g_h1[NB * HID];
__device__ float g_sum[HID];
__device__ float g_sumsq[HID];
__device__ int   g_barrier;

// ---------------------------------------------------------------------------
// 1) chunked segmented reduction (pool). r10 body (best measured), now with
//    __launch_bounds__(256, 5): cap regs ~52 -> 5 blocks/SM -> occ 62.5%
//    (was 58 regs / 4 blocks / 44.5% achieved; gather achieves 85% DRAM at
//    this occupancy region). Last TAIL_CACHED blocks load x cached (L2
//    handoff to reversed gather); others stream with __ldcs.
// ---------------------------------------------------------------------------
__global__ __launch_bounds__(256, 5) void pool_kernel(
    const float* __restrict__ x, const int* __restrict__ bidx,
    float* __restrict__ hpool, int n)
{
    int t  = threadIdx.x;
    int c4 = t & 63;        // float4 column 0..63
    int rg = t >> 6;        // row group 0..3

    int chunk = (n + POOL_BLOCKS - 1) / POOL_BLOCKS;
    int r0 = blockIdx.x * chunk;
    int r1 = min(r0 + chunk, n);
    if (r0 >= r1) return;

    bool cached = (blockIdx.x >= POOL_BLOCKS - TAIL_CACHED);

    const float4* x4 = reinterpret_cast<const float4*>(x);

    int cur = -1;
    float4 acc = make_float4(0.f, 0.f, 0.f, 0.f);

#define POOL_FLUSH()                                            \
    {                                                           \
        float* d = &hpool[(size_t)cur * HID + c4 * 4];          \
        atomicAdd(d + 0, acc.x); atomicAdd(d + 1, acc.y);       \
        atomicAdd(d + 2, acc.z); atomicAdd(d + 3, acc.w);       \
    }
#define POOL_STEP(G, V)                                                        \
    if ((G) != cur) {                                                          \
        if (cur >= 0) POOL_FLUSH();                                            \
        cur = (G); acc = (V);                                                  \
    } else { acc.x += (V).x; acc.y += (V).y; acc.z += (V).z; acc.w += (V).w; }

#define POOL_BODY(LOADX)                                                       \
    {                                                                          \
        int r = r0 + rg;                                                       \
        for (; r + 28 < r1; r += 32) {                                         \
            int g0 = __ldg(&bidx[r]);                                          \
            int g1 = __ldg(&bidx[r + 4]);                                      \
            int g2 = __ldg(&bidx[r + 8]);                                      \
            int g3 = __ldg(&bidx[r + 12]);                                     \
            int g4 = __ldg(&bidx[r + 16]);                                     \
            int g5 = __ldg(&bidx[r + 20]);                                     \
            int g6 = __ldg(&bidx[r + 24]);                                     \
            int g7 = __ldg(&bidx[r + 28]);                                     \
            float4 v0 = LOADX(&x4[(size_t)(r)      * H4 + c4]);                \
            float4 v1 = LOADX(&x4[(size_t)(r + 4)  * H4 + c4]);                \
            float4 v2 = LOADX(&x4[(size_t)(r + 8)  * H4 + c4]);                \
            float4 v3 = LOADX(&x4[(size_t)(r + 12) * H4 + c4]);                \
            float4 v4 = LOADX(&x4[(size_t)(r + 16) * H4 + c4]);                \
            float4 v5 = LOADX(&x4[(size_t)(r + 20) * H4 + c4]);                \
            float4 v6 = LOADX(&x4[(size_t)(r + 24) * H4 + c4]);                \
            float4 v7 = LOADX(&x4[(size_t)(r + 28) * H4 + c4]);                \
            POOL_STEP(g0, v0)                                                  \
            POOL_STEP(g1, v1)                                                  \
            POOL_STEP(g2, v2)                                                  \
            POOL_STEP(g3, v3)                                                  \
            POOL_STEP(g4, v4)                                                  \
            POOL_STEP(g5, v5)                                                  \
            POOL_STEP(g6, v6)                                                  \
            POOL_STEP(g7, v7)                                                  \
        }                                                                      \
        for (; r < r1; r += 4) {                                               \
            int g = __ldg(&bidx[r]);                                           \
            float4 v = LOADX(&x4[(size_t)r * H4 + c4]);                        \
            POOL_STEP(g, v)                                                    \
        }                                                                      \
    }

#define LDSTREAM(P) __ldcs(P)
#define LDCACHE(P)  __ldg(P)

    if (cached) {
        POOL_BODY(LDCACHE)
    } else {
        POOL_BODY(LDSTREAM)
    }
    if (cur >= 0) POOL_FLUSH();

#undef LDSTREAM
#undef LDCACHE
#undef POOL_BODY
#undef POOL_STEP
#undef POOL_FLUSH
}

// ---------------------------------------------------------------------------
// 2) FUSED MLP: phase 1 = gemm1 (h1 = (hpool+vnode)@W1+b1) + BN-stat atomics;
//    grid spin-barrier (all 128 blocks resident); phase 2 = BN scale/shift +
//    gemm2 (vn = relu(h1*scale+shift)@W2 + b2). W2 chunk-0 prefetched
//    before the spin. virtual_node folded into the A-tile load.
// ---------------------------------------------------------------------------
__global__ __launch_bounds__(256) void mlp_kernel(
    const float* __restrict__ A, const float* __restrict__ vnode,
    const float* __restrict__ W1, const float* __restrict__ b1,
    const float* __restrict__ gamma, const float* __restrict__ beta,
    const float* __restrict__ W2, const float* __restrict__ b2,
    float* __restrict__ h1, float* __restrict__ gsum,
    float* __restrict__ gsumsq, int* __restrict__ barrier,
    float* __restrict__ C)
{
    __shared__ float  As[2][32][33];
    __shared__ float4 Bs4[2][32][16];
    __shared__ float  red_s[16][64];
    __shared__ float  red_q[16][64];
    __shared__ float  scale_s[HID];
    __shared__ float  shift_s[HID];

    int t  = threadIdx.x;
    int tx = t & 15, ty = t >> 4;
    int m0 = blockIdx.y * 32;
    int n0 = blockIdx.x * 64;

    int arow = t >> 3, aq = t & 7;     // A: 32 rows x 8 float4
    int brow = t >> 4, bq = t & 15;    // B: 16 rows x 16 float4 (x2)

    // ===================== phase 1: gemm1 =====================
    {
        const float4* Ar = reinterpret_cast<const float4*>(&A[(size_t)(m0 + arow) * HID]);
        const float4* Vr = reinterpret_cast<const float4*>(&vnode[(size_t)(m0 + arow) * HID]);

        float4 a_r  = Ar[aq];
        float4 v_r  = Vr[aq];
        float4 b_r0 = *reinterpret_cast<const float4*>(&W1[(size_t)brow * HID + n0 + bq * 4]);
        float4 b_r1 = *reinterpret_cast<const float4*>(&W1[(size_t)(brow + 16) * HID + n0 + bq * 4]);
        As[0][arow][aq * 4 + 0] = a_r.x + v_r.x;
        As[0][arow][aq * 4 + 1] = a_r.y + v_r.y;
        As[0][arow][aq * 4 + 2] = a_r.z + v_r.z;
        As[0][arow][aq * 4 + 3] = a_r.w + v_r.w;
        Bs4[0][brow][bq]      = b_r0;
        Bs4[0][brow + 16][bq] = b_r1;
        __syncthreads();

        float acc[2][4];
#pragma unroll
        for (int i = 0; i < 2; i++)
#pragma unroll
            for (int j = 0; j < 4; j++) acc[i][j] = 0.f;

#pragma unroll
        for (int it = 0; it < 8; it++) {
            int cur = it & 1;
            if (it < 7) {
                int k1 = (it + 1) * 32;
                a_r  = Ar[(it + 1) * 8 + aq];
                v_r  = Vr[(it + 1) * 8 + aq];
                b_r0 = *reinterpret_cast<const float4*>(&W1[(size_t)(k1 + brow) * HID + n0 + bq * 4]);
                b_r1 = *reinterpret_cast<const float4*>(&W1[(size_t)(k1 + brow + 16) * HID + n0 + bq * 4]);
            }
#pragma unroll
            for (int kk = 0; kk < 32; kk++) {
                float4 bb = Bs4[cur][kk][tx];
                float a0 = As[cur][ty * 2 + 0][kk];
                float a1 = As[cur][ty * 2 + 1][kk];
                acc[0][0] += a0 * bb.x; acc[0][1] += a0 * bb.y; acc[0][2] += a0 * bb.z; acc[0][3] += a0 * bb.w;
                acc[1][0] += a1 * bb.x; acc[1][1] += a1 * bb.y; acc[1][2] += a1 * bb.z; acc[1][3] += a1 * bb.w;
            }
            if (it < 7) {
                int nxt = cur ^ 1;
                As[nxt][arow][aq * 4 + 0] = a_r.x + v_r.x;
                As[nxt][arow][aq * 4 + 1] = a_r.y + v_r.y;
                As[nxt][arow][aq * 4 + 2] = a_r.z + v_r.z;
                As[nxt][arow][aq * 4 + 3] = a_r.w + v_r.w;
                Bs4[nxt][brow][bq]      = b_r0;
                Bs4[nxt][brow + 16][bq] = b_r1;
            }
            __syncthreads();
        }

        float4 bv = *reinterpret_cast<const float4*>(&b1[n0 + tx * 4]);
        float v0[4], v1[4];
        v0[0] = acc[0][0] + bv.x; v0[1] = acc[0][1] + bv.y; v0[2] = acc[0][2] + bv.z; v0[3] = acc[0][3] + bv.w;
        v1[0] = acc[1][0] + bv.x; v1[1] = acc[1][1] + bv.y; v1[2] = acc[1][2] + bv.z; v1[3] = acc[1][3] + bv.w;

        *reinterpret_cast<float4*>(&h1[(size_t)(m0 + ty * 2 + 0) * HID + n0 + tx * 4]) =
            make_float4(v0[0], v0[1], v0[2], v0[3]);
        *reinterpret_cast<float4*>(&h1[(size_t)(m0 + ty * 2 + 1) * HID + n0 + tx * 4]) =
            make_float4(v1[0], v1[1], v1[2], v1[3]);

#pragma unroll
        for (int j = 0; j < 4; j++) {
            red_s[ty][tx * 4 + j] = v0[j] + v1[j];
            red_q[ty][tx * 4 + j] = v0[j] * v0[j] + v1[j] * v1[j];
        }
        __syncthreads();
        if (t < 64) {
            float S = 0.f, Q = 0.f;
#pragma unroll
            for (int g = 0; g < 16; g++) { S += red_s[g][t]; Q += red_q[g][t]; }
            atomicAdd(&gsum[n0 + t],   S);
            atomicAdd(&gsumsq[n0 + t], Q);
        }
    }

    // ================= grid barrier (all blocks resident) =================
    __threadfence();
    __syncthreads();
    if (t == 0) atomicAdd(barrier, 1);

    // prefetch W2 chunk 0 while waiting — independent of the barrier
    float4 b_r0 = *reinterpret_cast<const float4*>(&W2[(size_t)brow * HID + n0 + bq * 4]);
    float4 b_r1 = *reinterpret_cast<const float4*>(&W2[(size_t)(brow + 16) * HID + n0 + bq * 4]);

    if (t == 0) {
        while (*((volatile int*)barrier) < MLP_BLOCKS) { }
    }
    __syncthreads();
    __threadfence();

    // ===================== phase 2: BN + gemm2 =====================
    {
        float mean = gsum[t] * (1.f / NB);
        float var  = gsumsq[t] * (1.f / NB) - mean * mean;
        float sc   = gamma[t] * rsqrtf(var + EPS);
        scale_s[t] = sc;
        shift_s[t] = beta[t] - mean * sc;
    }
    __syncthreads();

    {
        const float4* Ar = reinterpret_cast<const float4*>(&h1[(size_t)(m0 + arow) * HID]);

        float4 a_r = Ar[aq];
        {
            int kc = aq * 4;
            As[0][arow][kc + 0] = fmaxf(a_r.x * scale_s[kc + 0] + shift_s[kc + 0], 0.f);
            As[0][arow][kc + 1] = fmaxf(a_r.y * scale_s[kc + 1] + shift_s[kc + 1], 0.f);
            As[0][arow][kc + 2] = fmaxf(a_r.z * scale_s[kc + 2] + shift_s[kc + 2], 0.f);
            As[0][arow][kc + 3] = fmaxf(a_r.w * scale_s[kc + 3] + shift_s[kc + 3], 0.f);
        }
        Bs4[0][brow][bq]      = b_r0;
        Bs4[0][brow + 16][bq] = b_r1;
        __syncthreads();

        float acc[2][4];
#pragma unroll
        for (int i = 0; i < 2; i++)
#pragma unroll
            for (int j = 0; j < 4; j++) acc[i][j] = 0.f;

#pragma unroll
        for (int it = 0; it < 8; it++) {
            int cur = it & 1;
            if (it < 7) {
                int k1 = (it + 1) * 32;
                a_r  = Ar[(it + 1) * 8 + aq];
                b_r0 = *reinterpret_cast<const float4*>(&W2[(size_t)(k1 + brow) * HID + n0 + bq * 4]);
                b_r1 = *reinterpret_cast<const float4*>(&W2[(size_t)(k1 + brow + 16) * HID + n0 + bq * 4]);
            }
#pragma unroll
            for (int kk = 0; kk < 32; kk++) {
                float4 bb = Bs4[cur][kk][tx];
                float a0 = As[cur][ty * 2 + 0][kk];
                float a1 = As[cur][ty * 2 + 1][kk];
                acc[0][0] += a0 * bb.x; acc[0][1] += a0 * bb.y; acc[0][2] += a0 * bb.z; acc[0][3] += a0 * bb.w;
                acc[1][0] += a1 * bb.x; acc[1][1] += a1 * bb.y; acc[1][2] += a1 * bb.z; acc[1][3] += a1 * bb.w;
            }
            if (it < 7) {
                int nxt = cur ^ 1;
                int kc  = (it + 1) * 32 + aq * 4;
                int sc0 = aq * 4;
                As[nxt][arow][sc0 + 0] = fmaxf(a_r.x * scale_s[kc + 0] + shift_s[kc + 0], 0.f);
                As[nxt][arow][sc0 + 1] = fmaxf(a_r.y * scale_s[kc + 1] + shift_s[kc + 1], 0.f);
                As[nxt][arow][sc0 + 2] = fmaxf(a_r.z * scale_s[kc + 2] + shift_s[kc + 2], 0.f);
                As[nxt][arow][sc0 + 3] = fmaxf(a_r.w * scale_s[kc + 3] + shift_s[kc + 3], 0.f);
                Bs4[nxt][brow][bq]      = b_r0;
                Bs4[nxt][brow + 16][bq] = b_r1;
            }
            __syncthreads();
        }

        float4 bv = *reinterpret_cast<const float4*>(&b2[n0 + tx * 4]);
#pragma unroll
        for (int i = 0; i < 2; i++) {
            float4 o;
            o.x = acc[i][0] + bv.x; o.y = acc[i][1] + bv.y;
            o.z = acc[i][2] + bv.z; o.w = acc[i][3] + bv.w;
            *reinterpret_cast<float4*>(&C[(size_t)(m0 + ty * 2 + i) * HID + n0 + tx * 4]) = o;
        }
    }
}

// ---------------------------------------------------------------------------
// 3) gather broadcast-add: x_out = x + vn[batch_idx]. Reversed block order
//    (L2 handoff from pool tail). ALSO amortizes next-call cleanup:
//      blocks 0..255: each thread zeroes one float4 of hpool (1MB total)
//      block 256:     zeroes gsum/gsumsq
//      block 257:     resets the mlp grid-barrier counter
// ---------------------------------------------------------------------------
__global__ __launch_bounds__(256) void gather_kernel(
    const float* __restrict__ x, const int* __restrict__ bidx,
    const float* __restrict__ vn, float* __restrict__ out,
    float* __restrict__ hpool, float* __restrict__ gsum,
    float* __restrict__ gsumsq, int* __restrict__ barrier,
    unsigned total4)
{
    // amortized cleanup for the next call
    if (blockIdx.x < 256u) {
        reinterpret_cast<float4*>(hpool)[blockIdx.x * 256u + threadIdx.x] =
            make_float4(0.f, 0.f, 0.f, 0.f);
    } else if (blockIdx.x == 256u) {
        gsum[threadIdx.x] = 0.f;
        gsumsq[threadIdx.x] = 0.f;
    } else if (blockIdx.x == 257u && threadIdx.x == 0u) {
        *barrier = 0;
    }

    const float4* x4  = reinterpret_cast<const float4*>(x);
    const float4* vn4 = reinterpret_cast<const float4*>(vn);
    float4*       o4  = reinterpret_cast<float4*>(out);

    unsigned rblk = gridDim.x - 1u - blockIdx.x;      // reversed chunk index
    unsigned base = rblk * 1024u + threadIdx.x;

    if (base + 768u < total4) {
        unsigned i0 = base, i1 = base + 256u, i2 = base + 512u, i3 = base + 768u;

        int g0 = __ldg(&bidx[i0 >> 6]);
        int g1 = __ldg(&bidx[i1 >> 6]);
        int g2 = __ldg(&bidx[i2 >> 6]);
        int g3 = __ldg(&bidx[i3 >> 6]);

        float4 a0 = __ldcs(&x4[i0]);
        float4 a1 = __ldcs(&x4[i1]);
        float4 a2 = __ldcs(&x4[i2]);
        float4 a3 = __ldcs(&x4[i3]);

        float4 v0 = vn4[(unsigned)g0 * H4 + (i0 & 63u)];
        float4 v1 = vn4[(unsigned)g1 * H4 + (i1 & 63u)];
        float4 v2 = vn4[(unsigned)g2 * H4 + (i2 & 63u)];
        float4 v3 = vn4[(unsigned)g3 * H4 + (i3 & 63u)];

        float4 o;
        o.x = a0.x + v0.x; o.y = a0.y + v0.y; o.z = a0.z + v0.z; o.w = a0.w + v0.w;
        __stcs(&o4[i0], o);
        o.x = a1.x + v1.x; o.y = a1.y + v1.y; o.z = a1.z + v1.z; o.w = a1.w + v1.w;
        __stcs(&o4[i1], o);
        o.x = a2.x + v2.x; o.y = a2.y + v2.y; o.z = a2.z + v2.z; o.w = a2.w + v2.w;
        __stcs(&o4[i2], o);
        o.x = a3.x + v3.x; o.y = a3.y + v3.y; o.z = a3.z + v3.z; o.w = a3.w + v3.w;
        __stcs(&o4[i3], o);
    } else {
#pragma unroll
        for (int j = 0; j < 4; j++) {
            unsigned i = base + (unsigned)j * 256u;
            if (i < total4) {
                int g = __ldg(&bidx[i >> 6]);
                float4 a = __ldcs(&x4[i]);
                float4 v = vn4[(unsigned)g * H4 + (i & 63u)];
                float4 o;
                o.x = a.x + v.x; o.y = a.y + v.y; o.z = a.z + v.z; o.w = a.w + v.w;
                __stcs(&o4[i], o);
            }
        }
    }
}

// ---------------------------------------------------------------------------
extern "C" void kernel_launch(void* const* d_in, const int* in_sizes, int n_in,
                              void* d_out, int out_size)
{
    const float* x     = (const float*)d_in[0];
    const int*   bidx  = (const int*)  d_in[1];
    const float* vnode = (const float*)d_in[2];
    const float* W1    = (const float*)d_in[3];
    const float* b1    = (const float*)d_in[4];
    const float* gamma = (const float*)d_in[5];
    const float* beta  = (const float*)d_in[6];
    const float* W2    = (const float*)d_in[7];
    const float* b2    = (const float*)d_in[8];

    int n = in_sizes[0] / HID;             // number of nodes

    float* out   = (float*)d_out;          // x_out: [n, H]
    float* vnout = out + (size_t)n * HID;  // vn: [B, H]

    float* hpool; cudaGetSymbolAddress((void**)&hpool, g_hpool);
    float* h1;    cudaGetSymbolAddress((void**)&h1,    g_h1);
    float* gsum;  cudaGetSymbolAddress((void**)&gsum,  g_sum);
    float* gsq;   cudaGetSymbolAddress((void**)&gsq,   g_sumsq);
    int*   bar;   cudaGetSymbolAddress((void**)&bar,   g_barrier);

    pool_kernel<<<POOL_BLOCKS, 256>>>(x, bidx, hpool, n);

    dim3 ggrid(HID / 64, NB / 32);         // (4, 32) = 128 blocks, all resident
    mlp_kernel<<<ggrid, 256>>>(hpool, vnode, W1, b1, gamma, beta, W2, b2,
                               h1, gsum, gsq, bar, vnout);

    unsigned total4 = (unsigned)n * H4;
    int blocks = (int)((total4 + 1023u) / 1024u);
    gather_kernel<<<blocks, 256>>>(x, bidx, vnout, out,
                                   hpool, gsum, gsq, bar, total4);
}

// round 16
// speedup vs baseline: 1.0145x; 1.0145x over previous
#include <cuda_runtime.h>
#include <cstdint>

#define HID 256
#define H4  64            // HID/4 float4 per row
#define NB  1024          // number of graphs
#define EPS 1e-5f
#define MLP_BLOCKS 128
#define POOL_BLOCKS 1776  // = 148 SMs x 4 blocks/SM x 3 -> zero wave quantization
#define TAIL_CACHED 400   // last pool blocks load x with L2-caching (~100MB)

// scratch (allocation-free rule: static __device__ globals; zero-initialized
// at module load; each call's gather re-zeroes them for the next call)
__device__ float g_hpool[NB * HID];
__device__ float g_h1[NB * HID];
__device__ float g_sum[HID];
__device__ float g_sumsq[HID];
__device__ int   g_barrier;

// ---------------------------------------------------------------------------
// 1) chunked segmented reduction (pool). r14 body (best measured: 58 regs,
//    NO occupancy cap — capping regs serialized the MLP-8 loads and lost BW).
//    POOL_BLOCKS=1776 = 592 residency slots x 3 chunks exactly: removes the
//    2048-block makespan quantization (272 slots ran 4 chunks vs avg 3.46).
//    Last TAIL_CACHED blocks load x cached (L2 handoff to reversed gather).
// ---------------------------------------------------------------------------
__global__ __launch_bounds__(256) void pool_kernel(
    const float* __restrict__ x, const int* __restrict__ bidx,
    float* __restrict__ hpool, int n)
{
    int t  = threadIdx.x;
    int c4 = t & 63;        // float4 column 0..63
    int rg = t >> 6;        // row group 0..3

    int chunk = (n + POOL_BLOCKS - 1) / POOL_BLOCKS;
    int r0 = blockIdx.x * chunk;
    int r1 = min(r0 + chunk, n);
    if (r0 >= r1) return;

    bool cached = (blockIdx.x >= POOL_BLOCKS - TAIL_CACHED);

    const float4* x4 = reinterpret_cast<const float4*>(x);

    int cur = -1;
    float4 acc = make_float4(0.f, 0.f, 0.f, 0.f);

#define POOL_FLUSH()                                            \
    {                                                           \
        float* d = &hpool[(size_t)cur * HID + c4 * 4];          \
        atomicAdd(d + 0, acc.x); atomicAdd(d + 1, acc.y);       \
        atomicAdd(d + 2, acc.z); atomicAdd(d + 3, acc.w);       \
    }
#define POOL_STEP(G, V)                                                        \
    if ((G) != cur) {                                                          \
        if (cur >= 0) POOL_FLUSH();                                            \
        cur = (G); acc = (V);                                                  \
    } else { acc.x += (V).x; acc.y += (V).y; acc.z += (V).z; acc.w += (V).w; }

#define POOL_BODY(LOADX)                                                       \
    {                                                                          \
        int r = r0 + rg;                                                       \
        for (; r + 28 < r1; r += 32) {                                         \
            int g0 = __ldg(&bidx[r]);                                          \
            int g1 = __ldg(&bidx[r + 4]);                                      \
            int g2 = __ldg(&bidx[r + 8]);                                      \
            int g3 = __ldg(&bidx[r + 12]);                                     \
            int g4 = __ldg(&bidx[r + 16]);                                     \
            int g5 = __ldg(&bidx[r + 20]);                                     \
            int g6 = __ldg(&bidx[r + 24]);                                     \
            int g7 = __ldg(&bidx[r + 28]);                                     \
            float4 v0 = LOADX(&x4[(size_t)(r)      * H4 + c4]);                \
            float4 v1 = LOADX(&x4[(size_t)(r + 4)  * H4 + c4]);                \
            float4 v2 = LOADX(&x4[(size_t)(r + 8)  * H4 + c4]);                \
            float4 v3 = LOADX(&x4[(size_t)(r + 12) * H4 + c4]);                \
            float4 v4 = LOADX(&x4[(size_t)(r + 16) * H4 + c4]);                \
            float4 v5 = LOADX(&x4[(size_t)(r + 20) * H4 + c4]);                \
            float4 v6 = LOADX(&x4[(size_t)(r + 24) * H4 + c4]);                \
            float4 v7 = LOADX(&x4[(size_t)(r + 28) * H4 + c4]);                \
            POOL_STEP(g0, v0)                                                  \
            POOL_STEP(g1, v1)                                                  \
            POOL_STEP(g2, v2)                                                  \
            POOL_STEP(g3, v3)                                                  \
            POOL_STEP(g4, v4)                                                  \
            POOL_STEP(g5, v5)                                                  \
            POOL_STEP(g6, v6)                                                  \
            POOL_STEP(g7, v7)                                                  \
        }                                                                      \
        for (; r < r1; r += 4) {                                               \
            int g = __ldg(&bidx[r]);                                           \
            float4 v = LOADX(&x4[(size_t)r * H4 + c4]);                        \
            POOL_STEP(g, v)                                                    \
        }                                                                      \
    }

#define LDSTREAM(P) __ldcs(P)
#define LDCACHE(P)  __ldg(P)

    if (cached) {
        POOL_BODY(LDCACHE)
    } else {
        POOL_BODY(LDSTREAM)
    }
    if (cur >= 0) POOL_FLUSH();

#undef LDSTREAM
#undef LDCACHE
#undef POOL_BODY
#undef POOL_STEP
#undef POOL_FLUSH
}

// ---------------------------------------------------------------------------
// 2) FUSED MLP: phase 1 = gemm1 (h1 = (hpool+vnode)@W1+b1) + BN-stat atomics;
//    grid spin-barrier (all 128 blocks resident); phase 2 = BN scale/shift +
//    gemm2 (vn = relu(h1*scale+shift)@W2 + b2). W2 chunk-0 prefetched
//    before the spin. virtual_node folded into the A-tile load.
// ---------------------------------------------------------------------------
__global__ __launch_bounds__(256) void mlp_kernel(
    const float* __restrict__ A, const float* __restrict__ vnode,
    const float* __restrict__ W1, const float* __restrict__ b1,
    const float* __restrict__ gamma, const float* __restrict__ beta,
    const float* __restrict__ W2, const float* __restrict__ b2,
    float* __restrict__ h1, float* __restrict__ gsum,
    float* __restrict__ gsumsq, int* __restrict__ barrier,
    float* __restrict__ C)
{
    __shared__ float  As[2][32][33];
    __shared__ float4 Bs4[2][32][16];
    __shared__ float  red_s[16][64];
    __shared__ float  red_q[16][64];
    __shared__ float  scale_s[HID];
    __shared__ float  shift_s[HID];

    int t  = threadIdx.x;
    int tx = t & 15, ty = t >> 4;
    int m0 = blockIdx.y * 32;
    int n0 = blockIdx.x * 64;

    int arow = t >> 3, aq = t & 7;     // A: 32 rows x 8 float4
    int brow = t >> 4, bq = t & 15;    // B: 16 rows x 16 float4 (x2)

    // ===================== phase 1: gemm1 =====================
    {
        const float4* Ar = reinterpret_cast<const float4*>(&A[(size_t)(m0 + arow) * HID]);
        const float4* Vr = reinterpret_cast<const float4*>(&vnode[(size_t)(m0 + arow) * HID]);

        float4 a_r  = Ar[aq];
        float4 v_r  = Vr[aq];
        float4 b_r0 = *reinterpret_cast<const float4*>(&W1[(size_t)brow * HID + n0 + bq * 4]);
        float4 b_r1 = *reinterpret_cast<const float4*>(&W1[(size_t)(brow + 16) * HID + n0 + bq * 4]);
        As[0][arow][aq * 4 + 0] = a_r.x + v_r.x;
        As[0][arow][aq * 4 + 1] = a_r.y + v_r.y;
        As[0][arow][aq * 4 + 2] = a_r.z + v_r.z;
        As[0][arow][aq * 4 + 3] = a_r.w + v_r.w;
        Bs4[0][brow][bq]      = b_r0;
        Bs4[0][brow + 16][bq] = b_r1;
        __syncthreads();

        float acc[2][4];
#pragma unroll
        for (int i = 0; i < 2; i++)
#pragma unroll
            for (int j = 0; j < 4; j++) acc[i][j] = 0.f;

#pragma unroll
        for (int it = 0; it < 8; it++) {
            int cur = it & 1;
            if (it < 7) {
                int k1 = (it + 1) * 32;
                a_r  = Ar[(it + 1) * 8 + aq];
                v_r  = Vr[(it + 1) * 8 + aq];
                b_r0 = *reinterpret_cast<const float4*>(&W1[(size_t)(k1 + brow) * HID + n0 + bq * 4]);
                b_r1 = *reinterpret_cast<const float4*>(&W1[(size_t)(k1 + brow + 16) * HID + n0 + bq * 4]);
            }
#pragma unroll
            for (int kk = 0; kk < 32; kk++) {
                float4 bb = Bs4[cur][kk][tx];
                float a0 = As[cur][ty * 2 + 0][kk];
                float a1 = As[cur][ty * 2 + 1][kk];
                acc[0][0] += a0 * bb.x; acc[0][1] += a0 * bb.y; acc[0][2] += a0 * bb.z; acc[0][3] += a0 * bb.w;
                acc[1][0] += a1 * bb.x; acc[1][1] += a1 * bb.y; acc[1][2] += a1 * bb.z; acc[1][3] += a1 * bb.w;
            }
            if (it < 7) {
                int nxt = cur ^ 1;
                As[nxt][arow][aq * 4 + 0] = a_r.x + v_r.x;
                As[nxt][arow][aq * 4 + 1] = a_r.y + v_r.y;
                As[nxt][arow][aq * 4 + 2] = a_r.z + v_r.z;
                As[nxt][arow][aq * 4 + 3] = a_r.w + v_r.w;
                Bs4[nxt][brow][bq]      = b_r0;
                Bs4[nxt][brow + 16][bq] = b_r1;
            }
            __syncthreads();
        }

        float4 bv = *reinterpret_cast<const float4*>(&b1[n0 + tx * 4]);
        float v0[4], v1[4];
        v0[0] = acc[0][0] + bv.x; v0[1] = acc[0][1] + bv.y; v0[2] = acc[0][2] + bv.z; v0[3] = acc[0][3] + bv.w;
        v1[0] = acc[1][0] + bv.x; v1[1] = acc[1][1] + bv.y; v1[2] = acc[1][2] + bv.z; v1[3] = acc[1][3] + bv.w;

        *reinterpret_cast<float4*>(&h1[(size_t)(m0 + ty * 2 + 0) * HID + n0 + tx * 4]) =
            make_float4(v0[0], v0[1], v0[2], v0[3]);
        *reinterpret_cast<float4*>(&h1[(size_t)(m0 + ty * 2 + 1) * HID + n0 + tx * 4]) =
            make_float4(v1[0], v1[1], v1[2], v1[3]);

#pragma unroll
        for (int j = 0; j < 4; j++) {
            red_s[ty][tx * 4 + j] = v0[j] + v1[j];
            red_q[ty][tx * 4 + j] = v0[j] * v0[j] + v1[j] * v1[j];
        }
        __syncthreads();
        if (t < 64) {
            float S = 0.f, Q = 0.f;
#pragma unroll
            for (int g = 0; g < 16; g++) { S += red_s[g][t]; Q += red_q[g][t]; }
            atomicAdd(&gsum[n0 + t],   S);
            atomicAdd(&gsumsq[n0 + t], Q);
        }
    }

    // ================= grid barrier (all blocks resident) =================
    __threadfence();
    __syncthreads();
    if (t == 0) atomicAdd(barrier, 1);

    // prefetch W2 chunk 0 while waiting — independent of the barrier
    float4 b_r0 = *reinterpret_cast<const float4*>(&W2[(size_t)brow * HID + n0 + bq * 4]);
    float4 b_r1 = *reinterpret_cast<const float4*>(&W2[(size_t)(brow + 16) * HID + n0 + bq * 4]);

    if (t == 0) {
        while (*((volatile int*)barrier) < MLP_BLOCKS) { }
    }
    __syncthreads();
    __threadfence();

    // ===================== phase 2: BN + gemm2 =====================
    {
        float mean = gsum[t] * (1.f / NB);
        float var  = gsumsq[t] * (1.f / NB) - mean * mean;
        float sc   = gamma[t] * rsqrtf(var + EPS);
        scale_s[t] = sc;
        shift_s[t] = beta[t] - mean * sc;
    }
    __syncthreads();

    {
        const float4* Ar = reinterpret_cast<const float4*>(&h1[(size_t)(m0 + arow) * HID]);

        float4 a_r = Ar[aq];
        {
            int kc = aq * 4;
            As[0][arow][kc + 0] = fmaxf(a_r.x * scale_s[kc + 0] + shift_s[kc + 0], 0.f);
            As[0][arow][kc + 1] = fmaxf(a_r.y * scale_s[kc + 1] + shift_s[kc + 1], 0.f);
            As[0][arow][kc + 2] = fmaxf(a_r.z * scale_s[kc + 2] + shift_s[kc + 2], 0.f);
            As[0][arow][kc + 3] = fmaxf(a_r.w * scale_s[kc + 3] + shift_s[kc + 3], 0.f);
        }
        Bs4[0][brow][bq]      = b_r0;
        Bs4[0][brow + 16][bq] = b_r1;
        __syncthreads();

        float acc[2][4];
#pragma unroll
        for (int i = 0; i < 2; i++)
#pragma unroll
            for (int j = 0; j < 4; j++) acc[i][j] = 0.f;

#pragma unroll
        for (int it = 0; it < 8; it++) {
            int cur = it & 1;
            if (it < 7) {
                int k1 = (it + 1) * 32;
                a_r  = Ar[(it + 1) * 8 + aq];
                b_r0 = *reinterpret_cast<const float4*>(&W2[(size_t)(k1 + brow) * HID + n0 + bq * 4]);
                b_r1 = *reinterpret_cast<const float4*>(&W2[(size_t)(k1 + brow + 16) * HID + n0 + bq * 4]);
            }
#pragma unroll
            for (int kk = 0; kk < 32; kk++) {
                float4 bb = Bs4[cur][kk][tx];
                float a0 = As[cur][ty * 2 + 0][kk];
                float a1 = As[cur][ty * 2 + 1][kk];
                acc[0][0] += a0 * bb.x; acc[0][1] += a0 * bb.y; acc[0][2] += a0 * bb.z; acc[0][3] += a0 * bb.w;
                acc[1][0] += a1 * bb.x; acc[1][1] += a1 * bb.y; acc[1][2] += a1 * bb.z; acc[1][3] += a1 * bb.w;
            }
            if (it < 7) {
                int nxt = cur ^ 1;
                int kc  = (it + 1) * 32 + aq * 4;
                int sc0 = aq * 4;
                As[nxt][arow][sc0 + 0] = fmaxf(a_r.x * scale_s[kc + 0] + shift_s[kc + 0], 0.f);
                As[nxt][arow][sc0 + 1] = fmaxf(a_r.y * scale_s[kc + 1] + shift_s[kc + 1], 0.f);
                As[nxt][arow][sc0 + 2] = fmaxf(a_r.z * scale_s[kc + 2] + shift_s[kc + 2], 0.f);
                As[nxt][arow][sc0 + 3] = fmaxf(a_r.w * scale_s[kc + 3] + shift_s[kc + 3], 0.f);
                Bs4[nxt][brow][bq]      = b_r0;
                Bs4[nxt][brow + 16][bq] = b_r1;
            }
            __syncthreads();
        }

        float4 bv = *reinterpret_cast<const float4*>(&b2[n0 + tx * 4]);
#pragma unroll
        for (int i = 0; i < 2; i++) {
            float4 o;
            o.x = acc[i][0] + bv.x; o.y = acc[i][1] + bv.y;
            o.z = acc[i][2] + bv.z; o.w = acc[i][3] + bv.w;
            *reinterpret_cast<float4*>(&C[(size_t)(m0 + ty * 2 + i) * HID + n0 + tx * 4]) = o;
        }
    }
}

// ---------------------------------------------------------------------------
// 3) gather broadcast-add: x_out = x + vn[batch_idx]. Reversed block order
//    (L2 handoff from pool tail). ALSO amortizes next-call cleanup:
//      blocks 0..255: each thread zeroes one float4 of hpool (1MB total)
//      block 256:     zeroes gsum/gsumsq
//      block 257:     resets the mlp grid-barrier counter
// ---------------------------------------------------------------------------
__global__ __launch_bounds__(256) void gather_kernel(
    const float* __restrict__ x, const int* __restrict__ bidx,
    const float* __restrict__ vn, float* __restrict__ out,
    float* __restrict__ hpool, float* __restrict__ gsum,
    float* __restrict__ gsumsq, int* __restrict__ barrier,
    unsigned total4)
{
    // amortized cleanup for the next call
    if (blockIdx.x < 256u) {
        reinterpret_cast<float4*>(hpool)[blockIdx.x * 256u + threadIdx.x] =
            make_float4(0.f, 0.f, 0.f, 0.f);
    } else if (blockIdx.x == 256u) {
        gsum[threadIdx.x] = 0.f;
        gsumsq[threadIdx.x] = 0.f;
    } else if (blockIdx.x == 257u && threadIdx.x == 0u) {
        *barrier = 0;
    }

    const float4* x4  = reinterpret_cast<const float4*>(x);
    const float4* vn4 = reinterpret_cast<const float4*>(vn);
    float4*       o4  = reinterpret_cast<float4*>(out);

    unsigned rblk = gridDim.x - 1u - blockIdx.x;      // reversed chunk index
    unsigned base = rblk * 1024u + threadIdx.x;

    if (base + 768u < total4) {
        unsigned i0 = base, i1 = base + 256u, i2 = base + 512u, i3 = base + 768u;

        int g0 = __ldg(&bidx[i0 >> 6]);
        int g1 = __ldg(&bidx[i1 >> 6]);
        int g2 = __ldg(&bidx[i2 >> 6]);
        int g3 = __ldg(&bidx[i3 >> 6]);

        float4 a0 = __ldcs(&x4[i0]);
        float4 a1 = __ldcs(&x4[i1]);
        float4 a2 = __ldcs(&x4[i2]);
        float4 a3 = __ldcs(&x4[i3]);

        float4 v0 = vn4[(unsigned)g0 * H4 + (i0 & 63u)];
        float4 v1 = vn4[(unsigned)g1 * H4 + (i1 & 63u)];
        float4 v2 = vn4[(unsigned)g2 * H4 + (i2 & 63u)];
        float4 v3 = vn4[(unsigned)g3 * H4 + (i3 & 63u)];

        float4 o;
        o.x = a0.x + v0.x; o.y = a0.y + v0.y; o.z = a0.z + v0.z; o.w = a0.w + v0.w;
        __stcs(&o4[i0], o);
        o.x = a1.x + v1.x; o.y = a1.y + v1.y; o.z = a1.z + v1.z; o.w = a1.w + v1.w;
        __stcs(&o4[i1], o);
        o.x = a2.x + v2.x; o.y = a2.y + v2.y; o.z = a2.z + v2.z; o.w = a2.w + v2.w;
        __stcs(&o4[i2], o);
        o.x = a3.x + v3.x; o.y = a3.y + v3.y; o.z = a3.z + v3.z; o.w = a3.w + v3.w;
        __stcs(&o4[i3], o);
    } else {
#pragma unroll
        for (int j = 0; j < 4; j++) {
            unsigned i = base + (unsigned)j * 256u;
            if (i < total4) {
                int g = __ldg(&bidx[i >> 6]);
                float4 a = __ldcs(&x4[i]);
                float4 v = vn4[(unsigned)g * H4 + (i & 63u)];
                float4 o;
                o.x = a.x + v.x; o.y = a.y + v.y; o.z = a.z + v.z; o.w = a.w + v.w;
                __stcs(&o4[i], o);
            }
        }
    }
}

// ---------------------------------------------------------------------------
extern "C" void kernel_launch(void* const* d_in, const int* in_sizes, int n_in,
                              void* d_out, int out_size)
{
    const float* x     = (const float*)d_in[0];
    const int*   bidx  = (const int*)  d_in[1];
    const float* vnode = (const float*)d_in[2];
    const float* W1    = (const float*)d_in[3];
    const float* b1    = (const float*)d_in[4];
    const float* gamma = (const float*)d_in[5];
    const float* beta  = (const float*)d_in[6];
    const float* W2    = (const float*)d_in[7];
    const float* b2    = (const float*)d_in[8];

    int n = in_sizes[0] / HID;             // number of nodes

    float* out   = (float*)d_out;          // x_out: [n, H]
    float* vnout = out + (size_t)n * HID;  // vn: [B, H]

    float* hpool; cudaGetSymbolAddress((void**)&hpool, g_hpool);
    float* h1;    cudaGetSymbolAddress((void**)&h1,    g_h1);
    float* gsum;  cudaGetSymbolAddress((void**)&gsum,  g_sum);
    float* gsq;   cudaGetSymbolAddress((void**)&gsq,   g_sumsq);
    int*   bar;   cudaGetSymbolAddress((void**)&bar,   g_barrier);

    pool_kernel<<<POOL_BLOCKS, 256>>>(x, bidx, hpool, n);

    dim3 ggrid(HID / 64, NB / 32);         // (4, 32) = 128 blocks, all resident
    mlp_kernel<<<ggrid, 256>>>(hpool, vnode, W1, b1, gamma, beta, W2, b2,
                               h1, gsum, gsq, bar, vnout);

    unsigned total4 = (unsigned)n * H4;
    int blocks = (int)((total4 + 1023u) / 1024u);
    gather_kernel<<<blocks, 256>>>(x, bidx, vnout, out,
                                   hpool, gsum, gsq, bar, total4);
}